// round 8
// baseline (speedup 1.0000x reference)
#include <cuda_runtime.h>

// Per-node weight accumulator (16B-aligned for float4 access). Zero at module
// load; phase 2 re-zeroes after consuming, so every replay starts from zeros.
__device__ __align__(16) float g_w[4 * 1024 * 1024];
__device__ double g_acc[8];
__device__ unsigned int g_count;

// ---------------- Phase 1: per-element det(J) scattered to node weights -----
// Persistent single-wave grid; 2 elements per iteration with all 6 coord
// gathers front-batched, then 6 interleaved REDG. 1/6 folded into finalize.
__global__ __launch_bounds__(256) void phase1_kernel(
    const float* __restrict__ coords,    // (N_NODES, 2)
    const int*   __restrict__ elements,  // (E, 3)
    int n_elements)
{
    const int T = gridDim.x * blockDim.x;
    const int n_pairs = (n_elements + 1) >> 1;

    for (int p = blockIdx.x * blockDim.x + threadIdx.x; p < n_pairs; p += T) {
        const int e0 = 2 * p;
        const bool has2 = (e0 + 1 < n_elements);
        const int* ep = elements + 3 * e0;

        const int i0 = __ldcs(ep + 0);
        const int i1 = __ldcs(ep + 1);
        const int i2 = __ldcs(ep + 2);
        const int i3 = has2 ? __ldcs(ep + 3) : i0;
        const int i4 = has2 ? __ldcs(ep + 4) : i1;
        const int i5 = has2 ? __ldcs(ep + 5) : i2;

        // 6 independent gathers in flight before any dependent math.
        const float2 c0 = *reinterpret_cast<const float2*>(coords + 2 * i0);
        const float2 c1 = *reinterpret_cast<const float2*>(coords + 2 * i1);
        const float2 c2 = *reinterpret_cast<const float2*>(coords + 2 * i2);
        const float2 c3 = *reinterpret_cast<const float2*>(coords + 2 * i3);
        const float2 c4 = *reinterpret_cast<const float2*>(coords + 2 * i4);
        const float2 c5 = *reinterpret_cast<const float2*>(coords + 2 * i5);

        const float det0 = (c1.x - c0.x) * (c2.y - c0.y)
                         - (c1.y - c0.y) * (c2.x - c0.x);
        const float det1 = (c4.x - c3.x) * (c5.y - c3.y)
                         - (c4.y - c3.y) * (c5.x - c3.x);

        atomicAdd(&g_w[i0], det0);   // REDG.F32, no return
        atomicAdd(&g_w[i1], det0);
        atomicAdd(&g_w[i2], det0);
        if (has2) {
            atomicAdd(&g_w[i3], det1);
            atomicAdd(&g_w[i4], det1);
            atomicAdd(&g_w[i5], det1);
        }
    }
}

// ---------------- Phase 2: dense dot  out[v] = (1/6) sum_n w[n]*vals[n][v] ---
// 4 consecutive nodes per thread: one float4 w load (no redundancy), eight
// float4 value loads, one float4 zero-store. ~9 load instrs per 4 nodes.
__global__ __launch_bounds__(256) void phase2_kernel(
    const float4* __restrict__ vals4,  // 2*N_NODES float4s
    float* __restrict__ out,
    int n_nodes, int nblocks)
{
    const int t = blockIdx.x * 256 + threadIdx.x;
    const int n0 = 4 * t;

    float4 accA = make_float4(0.f, 0.f, 0.f, 0.f);  // v0..3
    float4 accB = make_float4(0.f, 0.f, 0.f, 0.f);  // v4..7

    if (n0 + 4 <= n_nodes) {
        const float4 w4 = reinterpret_cast<const float4*>(g_w)[t];
        float4 v[8];
#pragma unroll
        for (int k = 0; k < 8; k++) v[k] = vals4[8 * t + k];
        reinterpret_cast<float4*>(g_w)[t] = make_float4(0.f, 0.f, 0.f, 0.f);

        accA.x = w4.x * v[0].x + w4.y * v[2].x + w4.z * v[4].x + w4.w * v[6].x;
        accA.y = w4.x * v[0].y + w4.y * v[2].y + w4.z * v[4].y + w4.w * v[6].y;
        accA.z = w4.x * v[0].z + w4.y * v[2].z + w4.z * v[4].z + w4.w * v[6].z;
        accA.w = w4.x * v[0].w + w4.y * v[2].w + w4.z * v[4].w + w4.w * v[6].w;
        accB.x = w4.x * v[1].x + w4.y * v[3].x + w4.z * v[5].x + w4.w * v[7].x;
        accB.y = w4.x * v[1].y + w4.y * v[3].y + w4.z * v[5].y + w4.w * v[7].y;
        accB.z = w4.x * v[1].z + w4.y * v[3].z + w4.z * v[5].z + w4.w * v[7].z;
        accB.w = w4.x * v[1].w + w4.y * v[3].w + w4.z * v[5].w + w4.w * v[7].w;
    } else if (n0 < n_nodes) {
        for (int n = n0; n < n_nodes; n++) {
            const float wn = g_w[n];
            g_w[n] = 0.0f;
            const float4 a = vals4[2 * n];
            const float4 b = vals4[2 * n + 1];
            accA.x += wn * a.x;  accA.y += wn * a.y;
            accA.z += wn * a.z;  accA.w += wn * a.w;
            accB.x += wn * b.x;  accB.y += wn * b.y;
            accB.z += wn * b.z;  accB.w += wn * b.w;
        }
    }

    // Warp xor-reduce of 8 floats.
#pragma unroll
    for (int off = 16; off >= 1; off >>= 1) {
        accA.x += __shfl_xor_sync(0xFFFFFFFFu, accA.x, off);
        accA.y += __shfl_xor_sync(0xFFFFFFFFu, accA.y, off);
        accA.z += __shfl_xor_sync(0xFFFFFFFFu, accA.z, off);
        accA.w += __shfl_xor_sync(0xFFFFFFFFu, accA.w, off);
        accB.x += __shfl_xor_sync(0xFFFFFFFFu, accB.x, off);
        accB.y += __shfl_xor_sync(0xFFFFFFFFu, accB.y, off);
        accB.z += __shfl_xor_sync(0xFFFFFFFFu, accB.z, off);
        accB.w += __shfl_xor_sync(0xFFFFFFFFu, accB.w, off);
    }

    __shared__ float sred[8][8];  // [warp][value]
    const int warp = threadIdx.x >> 5;
    const int lane = threadIdx.x & 31;
    if (lane == 0) {
        sred[warp][0] = accA.x;  sred[warp][1] = accA.y;
        sred[warp][2] = accA.z;  sred[warp][3] = accA.w;
        sred[warp][4] = accB.x;  sred[warp][5] = accB.y;
        sred[warp][6] = accB.z;  sred[warp][7] = accB.w;
    }
    __syncthreads();

    if (threadIdx.x < 8) {
        float sum = 0.0f;
#pragma unroll
        for (int w = 0; w < 8; w++) sum += sred[w][threadIdx.x];
        atomicAdd(&g_acc[threadIdx.x], (double)sum);
    }

    // Last-block-done: fused finalize + state reset (replay-deterministic).
    __shared__ bool is_last;
    __threadfence();
    if (threadIdx.x == 0) {
        unsigned int old = atomicInc(&g_count, (unsigned int)(nblocks - 1));
        is_last = (old == (unsigned int)(nblocks - 1));
    }
    __syncthreads();

    if (is_last && threadIdx.x < 8) {
        const double val = atomicAdd(&g_acc[threadIdx.x], 0.0);
        out[threadIdx.x] = (float)(val * (1.0 / 6.0));  // fold quad weight
        g_acc[threadIdx.x] = 0.0;
    }
}

extern "C" void kernel_launch(void* const* d_in, const int* in_sizes, int n_in,
                              void* d_out, int out_size) {
    const float* nodal_values = (const float*)d_in[0];
    const float* coords       = (const float*)d_in[1];
    const int*   elements     = (const int*)d_in[2];
    float* out = (float*)d_out;

    const int n_elements = in_sizes[2] / 3;
    const int n_nodes    = in_sizes[1] / 2;

    // Single-wave persistent grid: 148 SMs x 8 CTAs of 256 threads.
    phase1_kernel<<<1184, 256>>>(coords, elements, n_elements);

    const int p2_blocks = (n_nodes + 4 * 256 - 1) / (4 * 256);  // 977
    phase2_kernel<<<p2_blocks, 256>>>(
        reinterpret_cast<const float4*>(nodal_values), out, n_nodes, p2_blocks);
}